// round 11
// baseline (speedup 1.0000x reference)
#include <cuda_runtime.h>
#include <math.h>

#define NMAXA 1024
#define EPS2 1e-16f
#define COEF 14.399645478425668
#define SQRTPI 1.7724538509055160f
#define TABN 1024
#define TABXMAX 5.0f
#define GRID 592
#define NWARPS (GRID*8)

struct Params {
    float R[9];
    float cf[9];
    float Ld[3], invLd[3];
    float inv_s2eta, cut2r, cut2k, eta2h, self_c, pref4;
    int   nsh, nrr, twoR, nr, ntask, nrows, split, fastR, gskip, skip7;
    long long T;
};

__device__ double g_acc = 0.0;
__device__ unsigned int g_done = 0;

// Abramowitz-Stegun 7.1.26, abs err 1.5e-7 — table construction only.
__device__ __forceinline__ float erfc_as(float x) {
    float t = __fdividef(1.0f, fmaf(0.3275911f, x, 1.0f));
    float p = fmaf(t, 1.061405429f, -1.453152027f);
    p = fmaf(t, p, 1.421413741f);
    p = fmaf(t, p, -0.284496736f);
    p = fmaf(t, p, 0.254829592f);
    return t * p * __expf(-x*x);
}

// ---- packed f32x2 helpers (Blackwell FFMA2 path, PTX-only) ----
__device__ __forceinline__ unsigned long long pk2(float lo, float hi) {
    unsigned long long r;
    asm("mov.b64 %0, {%1, %2};" : "=l"(r) : "f"(lo), "f"(hi));
    return r;
}
__device__ __forceinline__ void upk2(unsigned long long v, float& lo, float& hi) {
    asm("mov.b64 {%0, %1}, %2;" : "=f"(lo), "=f"(hi) : "l"(v));
}
__device__ __forceinline__ unsigned long long mul2(unsigned long long a, unsigned long long b) {
    unsigned long long r; asm("mul.rn.f32x2 %0, %1, %2;" : "=l"(r) : "l"(a), "l"(b)); return r;
}
__device__ __forceinline__ unsigned long long fma2v(unsigned long long a, unsigned long long b, unsigned long long c) {
    unsigned long long r; asm("fma.rn.f32x2 %0, %1, %2, %3;" : "=l"(r) : "l"(a), "l"(b), "l"(c)); return r;
}
__device__ __forceinline__ unsigned long long add2(unsigned long long a, unsigned long long b) {
    unsigned long long r; asm("add.rn.f32x2 %0, %1, %2;" : "=l"(r) : "l"(a), "l"(b)); return r;
}

__global__ void __launch_bounds__(256, 4) ewald_kernel(
    const float* __restrict__ pos,
    const float* __restrict__ cell,
    const float* __restrict__ q,
    const float* __restrict__ sigt,
    const int*   __restrict__ spec,
    const int*   __restrict__ nsr,
    const int*   __restrict__ nsk,
    float* __restrict__ out,
    int n, int ntyp)
{
    __shared__ float4 sp[NMAXA];        // x, y, z, q
    __shared__ float  ssig[NMAXA];
    __shared__ float2 su[NMAXA];        // unit phase (cos, sin) — recip blocks only
    __shared__ float2 stab[TABN];       // erfc (value, slope) — real blocks only
    __shared__ float  sred34[34][8];
    __shared__ Params Ps;
    __shared__ double swred[8];

    const int tid = threadIdx.x;

    if (tid == 0) {
        float c[9];
        #pragma unroll
        for (int i = 0; i < 9; i++) c[i] = cell[i];
        float det = c[0]*(c[4]*c[8]-c[5]*c[7])
                  - c[1]*(c[3]*c[8]-c[5]*c[6])
                  + c[2]*(c[3]*c[7]-c[4]*c[6]);
        float vol = fabsf(det);
        const float PI_ = 3.14159265358979323846f;
        float eta  = powf(vol*vol/(float)n, 1.0f/6.0f) / sqrtf(2.0f*PI_);
        float s2lg = sqrtf(-2.0f*logf(1e-8f));
        float cutr = s2lg*eta, cutk = s2lg/eta;
        float id = 1.0f/det;
        float inv[9];
        inv[0] =  (c[4]*c[8]-c[5]*c[7])*id;
        inv[1] = -(c[1]*c[8]-c[2]*c[7])*id;
        inv[2] =  (c[1]*c[5]-c[2]*c[4])*id;
        inv[3] = -(c[3]*c[8]-c[5]*c[6])*id;
        inv[4] =  (c[0]*c[8]-c[2]*c[6])*id;
        inv[5] = -(c[0]*c[5]-c[2]*c[3])*id;
        inv[6] =  (c[3]*c[7]-c[4]*c[6])*id;
        inv[7] = -(c[0]*c[7]-c[1]*c[6])*id;
        inv[8] =  (c[0]*c[4]-c[1]*c[3])*id;
        #pragma unroll
        for (int i = 0; i < 3; i++)
            #pragma unroll
            for (int j = 0; j < 3; j++)
                Ps.R[i*3+j] = 2.0f*PI_*inv[j*3+i];
        #pragma unroll
        for (int i = 0; i < 9; i++) Ps.cf[i] = c[i];
        Ps.inv_s2eta = 1.0f/(sqrtf(2.0f)*eta);
        Ps.cut2r     = cutr*cutr;
        Ps.cut2k     = cutk*cutk;
        Ps.eta2h     = 0.5f*eta*eta;
        Ps.self_c    = -sqrtf(2.0f/PI_)/eta;
        Ps.pref4     = 4.0f*PI_/vol;

        int nrr = nsr[0];
        int two = 2*nrr + 1;
        Ps.nrr = nrr; Ps.twoR = two; Ps.nsh = two*two*two;

        float offd = fabsf(c[1])+fabsf(c[2])+fabsf(c[3])
                   + fabsf(c[5])+fabsf(c[6])+fabsf(c[7]);
        float dmin = fminf(fabsf(c[0]), fminf(fabsf(c[4]), fabsf(c[8])));
        Ps.fastR = (offd < 1e-6f*dmin) && (cutr < dmin) && (nrr >= 1);
        Ps.Ld[0] = c[0]; Ps.Ld[1] = c[4]; Ps.Ld[2] = c[8];
        Ps.invLd[0] = 1.0f/c[0]; Ps.invLd[1] = 1.0f/c[4]; Ps.invLd[2] = 1.0f/c[8];

        float smax2 = 0.f;
        for (int t = 0; t < ntyp; t++) {
            float s = sigt[t];
            smax2 = fmaxf(smax2, s*s);
        }
        float hmin2 = 0.25f*dmin*dmin;
        Ps.gskip = (hmin2 > 31.f*2.f*smax2);
        Ps.skip7 = (3.f*hmin2 > cutr*cutr);

        int nrk = nsk[0];
        Ps.nr = nrk;
        int nrows = 1 + nrk + nrk*(2*nrk+1);
        Ps.nrows = nrows;
        Ps.ntask = 2*nrows;
        Ps.split = (nrk == 8) && (nrows <= GRID/2) && (n <= NMAXA);
        Ps.T = (long long)n*(n+1)/2;
    }
    __syncthreads();

    const bool isRecip = Ps.split && ((int)blockIdx.x < Ps.nrows);

    // ---- role-specialized prologue ----
    for (int i = tid; i < n; i += 256)
        sp[i] = make_float4(pos[i*3+0], pos[i*3+1], pos[i*3+2], q[i]);
    if (isRecip) {
        const float R00=Ps.R[0], R01=Ps.R[1], R02=Ps.R[2];
        for (int i = tid; i < n; i += 256) {
            float ph = R00*pos[i*3+0] + R01*pos[i*3+1] + R02*pos[i*3+2];
            float sn, co; __sincosf(ph, &sn, &co);
            su[i] = make_float2(co, sn);
        }
    } else {
        for (int i = tid; i < n; i += 256) ssig[i] = sigt[spec[i]];
        const float dxx = TABXMAX / TABN;
        for (int t = tid; t < TABN; t += 256) {
            float y0 = erfc_as(t * dxx);
            float y1 = erfc_as((t + 1) * dxx);
            stab[t] = make_float2(y0, y1 - y0);
        }
    }
    __syncthreads();

    const float R00=Ps.R[0],R01=Ps.R[1],R02=Ps.R[2];
    const float R10=Ps.R[3],R11=Ps.R[4],R12=Ps.R[5];
    const float R20=Ps.R[6],R21=Ps.R[7],R22=Ps.R[8];
    const float cut2r = Ps.cut2r, cut2k = Ps.cut2k;
    const float eta2h = Ps.eta2h, self_c = Ps.self_c;
    const int   nr = Ps.nr;
    const long long T = Ps.T;
    const float TSCALE = (float)TABN / TABXMAX;
    const float TCLAMP = (float)(TABN - 2) + 0.999f;
    const float c1 = Ps.inv_s2eta * TSCALE;
    const float Lx=Ps.Ld[0], Ly=Ps.Ld[1], Lz=Ps.Ld[2];
    const float iLx=Ps.invLd[0], iLy=Ps.invLd[1], iLz=Ps.invLd[2];
    const int fast = Ps.fastR, gskip = Ps.gskip, skip7 = Ps.skip7;

    const int lane = tid & 31;
    const int wrp  = tid >> 5;

    double racc = 0.0, kacc = 0.0;

    auto pair_sum = [&](int i, int j, float gi) -> float {
        float4 ai = sp[i], aj = sp[j];
        float dx0 = aj.x-ai.x, dy0 = aj.y-ai.y, dz0 = aj.z-ai.z;
        float gj = ssig[j];
        float c2 = rsqrtf(2.f*(gi*gi + gj*gj)) * TSCALE;
        float sum = 0.f;
        if (fast) {
            float rx0 = dx0 - Lx*rintf(dx0*iLx);
            float ry0 = dy0 - Ly*rintf(dy0*iLy);
            float rz0 = dz0 - Lz*rintf(dz0*iLz);
            float rx1 = rx0 - copysignf(Lx, rx0);
            float ry1 = ry0 - copysignf(Ly, ry0);
            float rz1 = rz0 - copysignf(Lz, rz0);
            float ax0 = rx0*rx0, ax1 = rx1*rx1;
            float ay0 = ry0*ry0, ay1 = ry1*ry1;
            float az0 = rz0*rz0, az1 = rz1*rz1;
            {
                float d2 = ax0 + ay0 + az0;
                bool ok = (d2 > EPS2) && (d2 < cut2r);
                float d2c = fmaxf(d2, 1e-12f);
                float rd = rsqrtf(d2c);
                float dist = d2c*rd;
                float u1 = fminf(dist*c1, TCLAMP);
                float u2 = fminf(dist*c2, TCLAMP);
                int k1 = (int)u1, k2 = (int)u2;
                float2 e1 = stab[k1], e2 = stab[k2];
                float v = fmaf(u1-(float)k1, e1.y, e1.x)
                        - fmaf(u2-(float)k2, e2.y, e2.x);
                sum += ok ? v*rd : 0.f;
            }
            if (gskip) {
                #pragma unroll
                for (int t = 1; t < 7; t++) {
                    float d2 = ((t&1)?ax1:ax0) + ((t&2)?ay1:ay0) + ((t&4)?az1:az0);
                    bool ok = d2 < cut2r;
                    float rd = rsqrtf(d2);
                    float u1 = fminf(d2*rd*c1, TCLAMP);
                    int k1 = (int)u1;
                    float2 e1 = stab[k1];
                    float v = fmaf(u1-(float)k1, e1.y, e1.x);
                    sum += ok ? v*rd : 0.f;
                }
                if (!skip7) {
                    float d2 = ax1 + ay1 + az1;
                    bool ok = d2 < cut2r;
                    float rd = rsqrtf(d2);
                    float u1 = fminf(d2*rd*c1, TCLAMP);
                    int k1 = (int)u1;
                    float2 e1 = stab[k1];
                    float v = fmaf(u1-(float)k1, e1.y, e1.x);
                    sum += ok ? v*rd : 0.f;
                }
            } else {
                #pragma unroll
                for (int t = 1; t < 8; t++) {
                    float d2 = ((t&1)?ax1:ax0) + ((t&2)?ay1:ay0) + ((t&4)?az1:az0);
                    bool ok = d2 < cut2r;
                    float rd = rsqrtf(d2);
                    float dist = d2*rd;
                    float u1 = fminf(dist*c1, TCLAMP);
                    float u2 = fminf(dist*c2, TCLAMP);
                    int k1 = (int)u1, k2 = (int)u2;
                    float2 e1 = stab[k1], e2 = stab[k2];
                    float v = fmaf(u1-(float)k1, e1.y, e1.x)
                            - fmaf(u2-(float)k2, e2.y, e2.x);
                    sum += ok ? v*rd : 0.f;
                }
            }
        } else {
            int two = Ps.twoR, nrr = Ps.nrr, nsh = Ps.nsh;
            for (int s = 0; s < nsh; s++) {
                int a = s/(two*two) - nrr;
                int r2 = s%(two*two);
                int b = r2/two - nrr;
                int c3 = r2%two - nrr;
                float dx = dx0 + a*Ps.cf[0] + b*Ps.cf[3] + c3*Ps.cf[6];
                float dy = dy0 + a*Ps.cf[1] + b*Ps.cf[4] + c3*Ps.cf[7];
                float dz = dz0 + a*Ps.cf[2] + b*Ps.cf[5] + c3*Ps.cf[8];
                float d2 = fmaf(dx,dx, fmaf(dy,dy, dz*dz));
                bool ok = (d2 > EPS2) && (d2 < cut2r);
                float d2c = fmaxf(d2, 1e-12f);
                float rd = rsqrtf(d2c);
                float dist = d2c*rd;
                float u1 = fminf(dist*c1, TCLAMP);
                float u2 = fminf(dist*c2, TCLAMP);
                int k1 = (int)u1, k2 = (int)u2;
                float2 e1 = stab[k1], e2 = stab[k2];
                float v = fmaf(u1-(float)k1, e1.y, e1.x)
                        - fmaf(u2-(float)k2, e2.y, e2.x);
                sum += ok ? v*rd : 0.f;
            }
        }
        return sum;
    };

    auto decode = [&](long long p, int& i, int& j) {
        float tnf = 2.f*(float)n + 1.f;
        long long discl = (long long)(2*n+1)*(2*n+1) - 8*p;
        i = (int)((tnf - sqrtf((float)discl)) * 0.5f);
        if (i < 0) i = 0;
        if (i >= n) i = n - 1;
        long long off = (long long)i*n - (long long)i*(i-1)/2;
        while (p < off) { i--; off = (long long)i*n - (long long)i*(i-1)/2; }
        while (p >= off + (long long)(n - i)) { off += (n - i); i++; }
        j = i + (int)(p - off);
    };

    if (Ps.split) {
        const int nrows = Ps.nrows;
        if (isRecip) {
            // ===== block-cooperative recip row, packed f32x2 dual chains =====
            int row = blockIdx.x;
            int b, cc; float wt;
            if (row == 0)          { b = 0;   cc = 0; wt = 1.f; }
            else if (row <= nr)    { b = row; cc = 0; wt = 2.f; }
            else {
                int t2 = row - 1 - nr, two = 2*nr + 1;
                cc = t2/two + 1; b = t2%two - nr;
                wt = 2.f;
            }
            float ux = b*R10 + cc*R20, uy = b*R11 + cc*R21, uz = b*R12 + cc*R22;
            float s00 = R00*R00 + R01*R01 + R02*R02;
            float s0u = R00*ux + R01*uy + R02*uz;
            float uu  = ux*ux + uy*uy + uz*uz;
            float a1f = floorf(-s0u/s00);
            float mink2 = 1e30f;
            #pragma unroll
            for (int t2 = 0; t2 < 2; t2++) {
                float af = fminf(fmaxf(a1f + t2, -8.f), 8.f);
                mink2 = fminf(mink2, fmaf(af, fmaf(af, s00, 2.f*s0u), uu));
            }
            if (mink2 < cut2k) {
                unsigned long long SC[8], SS[8];
                #pragma unroll
                for (int t2 = 0; t2 < 8; t2++) { SC[t2] = 0ull; SS[t2] = 0ull; }
                float Sc8 = 0.f, Ss8 = 0.f;
                float bf = (float)b, cf2 = (float)cc;
                for (int i = tid; i < n; i += 256) {
                    float4 a = sp[i];
                    float th = bf*(R10*a.x + R11*a.y + R12*a.z)
                             + cf2*(R20*a.x + R21*a.y + R22*a.z);
                    float sn, co; __sincosf(th, &sn, &co);
                    float pr = a.w*co, pim = a.w*sn;
                    Sc8 += pr; Ss8 += pim;
                    float2 u2v = su[i];
                    unsigned long long U  = pk2(u2v.x,  u2v.x);
                    unsigned long long NV = pk2(-u2v.y, u2v.y);   // −V for X update
                    unsigned long long Vp = pk2(u2v.y, -u2v.y);   //  V for Y update
                    unsigned long long X = pk2(pr, pr), Y = pk2(pim, pim);
                    #pragma unroll
                    for (int a2 = 0; a2 < 8; a2++) {
                        unsigned long long Xn = fma2v(Y, NV, mul2(X, U)); // X·U − Y·V
                        unsigned long long Yn = fma2v(Y, U,  mul2(X, Vp)); // X·V + Y·U
                        X = Xn; Y = Yn;
                        SC[a2] = add2(SC[a2], X);
                        SS[a2] = add2(SS[a2], Y);
                    }
                }
                // unpack to 17 Sc / 17 Ss (lo lane = +a, hi lane = −a)
                float Sc[17], Ss[17];
                Sc[8] = Sc8; Ss[8] = Ss8;
                #pragma unroll
                for (int a2 = 0; a2 < 8; a2++) {
                    float lo, hi;
                    upk2(SC[a2], lo, hi); Sc[9+a2] = lo; Sc[7-a2] = hi;
                    upk2(SS[a2], lo, hi); Ss[9+a2] = lo; Ss[7-a2] = hi;
                }
                #pragma unroll
                for (int v = 0; v < 17; v++) {
                    float scv = Sc[v], ssv = Ss[v];
                    #pragma unroll
                    for (int o = 16; o > 0; o >>= 1) {
                        scv += __shfl_xor_sync(0xffffffffu, scv, o);
                        ssv += __shfl_xor_sync(0xffffffffu, ssv, o);
                    }
                    if (lane == 0) { sred34[v][wrp] = scv; sred34[17+v][wrp] = ssv; }
                }
                __syncthreads();
                if (wrp == 0) {
                    float term = 0.f;
                    if (lane < 17) {
                        float scv = 0.f, ssv = 0.f;
                        #pragma unroll
                        for (int w2 = 0; w2 < 8; w2++) {
                            scv += sred34[lane][w2];
                            ssv += sred34[17+lane][w2];
                        }
                        float af = (float)(lane - 8);
                        float kx = af*R00+ux, ky = af*R01+uy, kz = af*R02+uz;
                        float kl2 = kx*kx + ky*ky + kz*kz;
                        if (kl2 > EPS2 && kl2 < cut2k)
                            term = wt * __expf(-eta2h*kl2) / kl2 * (scv*scv + ssv*ssv);
                    }
                    #pragma unroll
                    for (int o = 16; o > 0; o >>= 1)
                        term += __shfl_xor_sync(0xffffffffu, term, o);
                    if (lane == 0) kacc = (double)term;
                }
            }
        } else {
            // ===== real pairs: contiguous per-block, per-thread chunks =====
            int rb = blockIdx.x - nrows;
            int NB = GRID - nrows;
            long long lo = ((long long)rb * T) / NB;
            long long hi = ((long long)(rb+1) * T) / NB;
            int cnt = (int)(hi - lo);
            int cpt = (cnt + 255) >> 8;
            long long start = lo + (long long)tid * cpt;
            long long end = start + cpt; if (end > hi) end = hi;
            if (start < end) {
                int i, j;
                decode(start, i, j);
                float racc_f = 0.f;
                for (long long p = start; p < end; p++) {
                    float gi = ssig[i];
                    float sum = pair_sum(i, j, gi);
                    float wq = sp[i].w * sp[j].w;
                    if (i == j) racc_f += wq*(sum + self_c + 1.f/(SQRTPI*gi));
                    else        racc_f += 2.f*wq*sum;
                    j++;
                    if (j == n) { i++; j = i; }
                }
                racc = (double)racc_f;
            }
        }
    } else {
        // ===== generic fallback: round-9 scheme =====
        const int gw = (blockIdx.x << 3) + wrp;
        {
            float kacc_f = 0.f;
            const int Ntask = Ps.ntask;
            int t_lo = (int)(((long long)gw * Ntask) / NWARPS);
            int t_hi = (int)(((long long)(gw+1) * Ntask) / NWARPS);
            for (int idx = t_lo; idx < t_hi; idx++) {
                int row = idx >> 1, half = idx & 1;
                int b, cc; float wt;
                if (row == 0)          { b = 0;   cc = 0; wt = 1.f; }
                else if (row <= nr)    { b = row; cc = 0; wt = 2.f; }
                else {
                    int t2 = row - 1 - nr, two = 2*nr + 1;
                    cc = t2/two + 1; b = t2%two - nr;
                    wt = 2.f;
                }
                int alo = half ? -nr : 0;
                int ahi = half ? -1  : nr;
                float ux = b*R10 + cc*R20, uy = b*R11 + cc*R21, uz = b*R12 + cc*R22;
                float s00 = R00*R00 + R01*R01 + R02*R02;
                float s0u = R00*ux + R01*uy + R02*uz;
                float uu  = ux*ux + uy*uy + uz*uz;
                float a1f = floorf(-s0u/s00);
                float mink2 = 1e30f;
                #pragma unroll
                for (int t2 = 0; t2 < 2; t2++) {
                    float af = fminf(fmaxf(a1f + t2, (float)alo), (float)ahi);
                    mink2 = fminf(mink2, fmaf(af, fmaf(af, s00, 2.f*s0u), uu));
                }
                if (mink2 >= cut2k) continue;
                for (int a = alo; a <= ahi; a++) {
                    float af = (float)a;
                    float kx = af*R00+ux, ky = af*R01+uy, kz = af*R02+uz;
                    float kl2 = kx*kx + ky*ky + kz*kz;
                    if (!(kl2 > EPS2 && kl2 < cut2k)) continue;
                    float scv = 0.f, ssv = 0.f;
                    for (int i = lane; i < n; i += 32) {
                        float4 a3 = sp[i];
                        float th = kx*a3.x + ky*a3.y + kz*a3.z;
                        float sn, co; __sincosf(th, &sn, &co);
                        scv = fmaf(a3.w, co, scv);
                        ssv = fmaf(a3.w, sn, ssv);
                    }
                    #pragma unroll
                    for (int o = 16; o > 0; o >>= 1) {
                        scv += __shfl_xor_sync(0xffffffffu, scv, o);
                        ssv += __shfl_xor_sync(0xffffffffu, ssv, o);
                    }
                    if (lane == 0)
                        kacc_f += wt * __expf(-eta2h*kl2) / kl2
                                  * (scv*scv + ssv*ssv);
                }
            }
            kacc = (double)kacc_f;
        }
        {
            const long long CH = 2;
            const long long G2 = (long long)GRID * 256 * CH;
            for (long long p0 = ((long long)blockIdx.x*256 + tid)*CH; p0 < T; p0 += G2) {
                int i, j;
                decode(p0, i, j);
                float racc_f = 0.f;
                #pragma unroll
                for (int u = 0; u < (int)CH; u++) {
                    if (p0 + u >= T) break;
                    float gi = ssig[i];
                    float sum = pair_sum(i, j, gi);
                    float wq = sp[i].w * sp[j].w;
                    if (i == j) racc_f += wq*(sum + self_c + 1.f/(SQRTPI*gi));
                    else        racc_f += 2.f*wq*sum;
                    j++;
                    if (j == n) { i++; j = i; }
                }
                racc += (double)racc_f;
            }
        }
    }

    // ---- reduction ----
    double tot = 0.5*COEF*(racc + (double)Ps.pref4 * kacc);
    #pragma unroll
    for (int o = 16; o > 0; o >>= 1)
        tot += __shfl_xor_sync(0xffffffffu, tot, o);
    __syncthreads();
    if (lane == 0) swred[wrp] = tot;
    __syncthreads();
    if (tid == 0) {
        double s = swred[0]+swred[1]+swred[2]+swred[3]
                 + swred[4]+swred[5]+swred[6]+swred[7];
        atomicAdd(&g_acc, s);
        __threadfence();
        unsigned t = atomicAdd(&g_done, 1u);
        if (t == gridDim.x - 1) {
            double v = atomicAdd(&g_acc, 0.0);
            out[0] = (float)v;
            g_acc = 0.0;
            g_done = 0u;
        }
    }
}

extern "C" void kernel_launch(void* const* d_in, const int* in_sizes, int n_in,
                              void* d_out, int out_size)
{
    const float* pos     = (const float*)d_in[0];
    const float* cell    = (const float*)d_in[1];
    const float* charges = (const float*)d_in[2];
    const float* sigt    = (const float*)d_in[3];
    const int*   spec    = (const int*)d_in[4];
    const int*   nsr     = (const int*)d_in[5];
    const int*   nsk     = (const int*)d_in[6];
    int n = in_sizes[0] / 3;
    int ntyp = in_sizes[3];

    ewald_kernel<<<GRID, 256>>>(pos, cell, charges, sigt, spec, nsr, nsk,
                                (float*)d_out, n, ntyp);
}

// round 13
// speedup vs baseline: 1.2654x; 1.2654x over previous
#include <cuda_runtime.h>
#include <math.h>

#define NMAXA 1024
#define EPS2 1e-16f
#define COEF 14.399645478425668
#define SQRTPI 1.7724538509055160f
#define TABN 1024
#define TABXMAX 5.0f
#define GRID 592
#define NWARPS (GRID*8)

struct Params {
    float R[9];
    float cf[9];
    float Ld[3], invLd[3];
    float inv_s2eta, cut2r, cut2k, eta2h, self_c, pref4;
    int   nsh, nrr, twoR, nr, ntask, nrows, split, fastR, gskip, skip7;
    long long T;
};

__device__ double g_acc = 0.0;
__device__ unsigned int g_done = 0;

// Abramowitz-Stegun 7.1.26, abs err 1.5e-7 — table construction only.
__device__ __forceinline__ float erfc_as(float x) {
    float t = __fdividef(1.0f, fmaf(0.3275911f, x, 1.0f));
    float p = fmaf(t, 1.061405429f, -1.453152027f);
    p = fmaf(t, p, 1.421413741f);
    p = fmaf(t, p, -0.284496736f);
    p = fmaf(t, p, 0.254829592f);
    return t * p * __expf(-x*x);
}

__global__ void __launch_bounds__(256, 4) ewald_kernel(
    const float* __restrict__ pos,
    const float* __restrict__ cell,
    const float* __restrict__ q,
    const float* __restrict__ sigt,
    const int*   __restrict__ spec,
    const int*   __restrict__ nsr,
    const int*   __restrict__ nsk,
    float* __restrict__ out,
    int n, int ntyp)
{
    __shared__ float4 sp[NMAXA];        // x, y, z, q
    __shared__ float  ssig[NMAXA];      // real blocks only
    __shared__ float2 su[NMAXA];        // unit phase — recip blocks only
    __shared__ float2 stab[TABN];       // erfc (value, slope) — real blocks only
    __shared__ float  sred34[34][8];
    __shared__ Params Ps;
    __shared__ double swred[8];

    const int tid = threadIdx.x;

    if (tid == 0) {
        float c[9];
        #pragma unroll
        for (int i = 0; i < 9; i++) c[i] = cell[i];
        float det = c[0]*(c[4]*c[8]-c[5]*c[7])
                  - c[1]*(c[3]*c[8]-c[5]*c[6])
                  + c[2]*(c[3]*c[7]-c[4]*c[6]);
        float vol = fabsf(det);
        const float PI_ = 3.14159265358979323846f;
        float eta  = powf(vol*vol/(float)n, 1.0f/6.0f) / sqrtf(2.0f*PI_);
        float s2lg = sqrtf(-2.0f*logf(1e-8f));
        float cutr = s2lg*eta, cutk = s2lg/eta;
        float id = 1.0f/det;
        float inv[9];
        inv[0] =  (c[4]*c[8]-c[5]*c[7])*id;
        inv[1] = -(c[1]*c[8]-c[2]*c[7])*id;
        inv[2] =  (c[1]*c[5]-c[2]*c[4])*id;
        inv[3] = -(c[3]*c[8]-c[5]*c[6])*id;
        inv[4] =  (c[0]*c[8]-c[2]*c[6])*id;
        inv[5] = -(c[0]*c[5]-c[2]*c[3])*id;
        inv[6] =  (c[3]*c[7]-c[4]*c[6])*id;
        inv[7] = -(c[0]*c[7]-c[1]*c[6])*id;
        inv[8] =  (c[0]*c[4]-c[1]*c[3])*id;
        #pragma unroll
        for (int i = 0; i < 3; i++)
            #pragma unroll
            for (int j = 0; j < 3; j++)
                Ps.R[i*3+j] = 2.0f*PI_*inv[j*3+i];
        #pragma unroll
        for (int i = 0; i < 9; i++) Ps.cf[i] = c[i];
        Ps.inv_s2eta = 1.0f/(sqrtf(2.0f)*eta);
        Ps.cut2r     = cutr*cutr;
        Ps.cut2k     = cutk*cutk;
        Ps.eta2h     = 0.5f*eta*eta;
        Ps.self_c    = -sqrtf(2.0f/PI_)/eta;
        Ps.pref4     = 4.0f*PI_/vol;

        int nrr = nsr[0];
        int two = 2*nrr + 1;
        Ps.nrr = nrr; Ps.twoR = two; Ps.nsh = two*two*two;

        float offd = fabsf(c[1])+fabsf(c[2])+fabsf(c[3])
                   + fabsf(c[5])+fabsf(c[6])+fabsf(c[7]);
        float dmin = fminf(fabsf(c[0]), fminf(fabsf(c[4]), fabsf(c[8])));
        Ps.fastR = (offd < 1e-6f*dmin) && (cutr < dmin) && (nrr >= 1);
        Ps.Ld[0] = c[0]; Ps.Ld[1] = c[4]; Ps.Ld[2] = c[8];
        Ps.invLd[0] = 1.0f/c[0]; Ps.invLd[1] = 1.0f/c[4]; Ps.invLd[2] = 1.0f/c[8];

        float smax2 = 0.f;
        for (int t = 0; t < ntyp; t++) {
            float s = sigt[t];
            smax2 = fmaxf(smax2, s*s);
        }
        float hmin2 = 0.25f*dmin*dmin;
        Ps.gskip = (hmin2 > 31.f*2.f*smax2);
        Ps.skip7 = (3.f*hmin2 > cutr*cutr);

        int nrk = nsk[0];
        Ps.nr = nrk;
        int nrows = 1 + nrk + nrk*(2*nrk+1);
        Ps.nrows = nrows;
        Ps.ntask = 2*nrows;
        Ps.split = (nrk == 8) && (nrows <= GRID/2) && (n <= NMAXA);
        Ps.T = (long long)n*(n+1)/2;
    }
    __syncthreads();

    const bool isRecip = Ps.split && ((int)blockIdx.x < Ps.nrows);

    // ---- role-specialized prologue ----
    for (int i = tid; i < n; i += 256)
        sp[i] = make_float4(pos[i*3+0], pos[i*3+1], pos[i*3+2], q[i]);
    const bool needReal = !Ps.split || !isRecip;
    if (isRecip || !Ps.split) {
        const float R00=Ps.R[0], R01=Ps.R[1], R02=Ps.R[2];
        for (int i = tid; i < n; i += 256) {
            float ph = R00*pos[i*3+0] + R01*pos[i*3+1] + R02*pos[i*3+2];
            float sn, co; __sincosf(ph, &sn, &co);
            su[i] = make_float2(co, sn);
        }
    }
    if (needReal) {
        for (int i = tid; i < n; i += 256) ssig[i] = sigt[spec[i]];
        const float dxx = TABXMAX / TABN;
        for (int t = tid; t < TABN; t += 256) {
            float y0 = erfc_as(t * dxx);
            float y1 = erfc_as((t + 1) * dxx);
            stab[t] = make_float2(y0, y1 - y0);
        }
    }
    __syncthreads();

    const float R00=Ps.R[0],R01=Ps.R[1],R02=Ps.R[2];
    const float R10=Ps.R[3],R11=Ps.R[4],R12=Ps.R[5];
    const float R20=Ps.R[6],R21=Ps.R[7],R22=Ps.R[8];
    const float cut2r = Ps.cut2r, cut2k = Ps.cut2k;
    const float eta2h = Ps.eta2h, self_c = Ps.self_c;
    const int   nr = Ps.nr;
    const long long T = Ps.T;
    const float TSCALE = (float)TABN / TABXMAX;
    const float TCLAMP = (float)(TABN - 2) + 0.999f;
    const float c1 = Ps.inv_s2eta * TSCALE;
    const float Lx=Ps.Ld[0], Ly=Ps.Ld[1], Lz=Ps.Ld[2];
    const float iLx=Ps.invLd[0], iLy=Ps.invLd[1], iLz=Ps.invLd[2];
    const int fast = Ps.fastR, gskip = Ps.gskip, skip7 = Ps.skip7;

    const int lane = tid & 31;
    const int wrp  = tid >> 5;

    double racc = 0.0, kacc = 0.0;

    auto pair_sum = [&](int i, int j, float gi) -> float {
        float4 ai = sp[i], aj = sp[j];
        float dx0 = aj.x-ai.x, dy0 = aj.y-ai.y, dz0 = aj.z-ai.z;
        float gj = ssig[j];
        float c2 = rsqrtf(2.f*(gi*gi + gj*gj)) * TSCALE;
        float sum = 0.f;
        if (fast) {
            float rx0 = dx0 - Lx*rintf(dx0*iLx);
            float ry0 = dy0 - Ly*rintf(dy0*iLy);
            float rz0 = dz0 - Lz*rintf(dz0*iLz);
            float rx1 = rx0 - copysignf(Lx, rx0);
            float ry1 = ry0 - copysignf(Ly, ry0);
            float rz1 = rz0 - copysignf(Lz, rz0);
            float ax0 = rx0*rx0, ax1 = rx1*rx1;
            float ay0 = ry0*ry0, ay1 = ry1*ry1;
            float az0 = rz0*rz0, az1 = rz1*rz1;
            {
                float d2 = ax0 + ay0 + az0;
                bool ok = (d2 > EPS2) && (d2 < cut2r);
                float d2c = fmaxf(d2, 1e-12f);
                float rd = rsqrtf(d2c);
                float dist = d2c*rd;
                float u1 = fminf(dist*c1, TCLAMP);
                float u2 = fminf(dist*c2, TCLAMP);
                int k1 = (int)u1, k2 = (int)u2;
                float2 e1 = stab[k1], e2 = stab[k2];
                float v = fmaf(u1-(float)k1, e1.y, e1.x)
                        - fmaf(u2-(float)k2, e2.y, e2.x);
                sum += ok ? v*rd : 0.f;
            }
            if (gskip) {
                #pragma unroll
                for (int t = 1; t < 7; t++) {
                    float d2 = ((t&1)?ax1:ax0) + ((t&2)?ay1:ay0) + ((t&4)?az1:az0);
                    bool ok = d2 < cut2r;
                    float rd = rsqrtf(d2);
                    float u1 = fminf(d2*rd*c1, TCLAMP);
                    int k1 = (int)u1;
                    float2 e1 = stab[k1];
                    float v = fmaf(u1-(float)k1, e1.y, e1.x);
                    sum += ok ? v*rd : 0.f;
                }
                if (!skip7) {
                    float d2 = ax1 + ay1 + az1;
                    bool ok = d2 < cut2r;
                    float rd = rsqrtf(d2);
                    float u1 = fminf(d2*rd*c1, TCLAMP);
                    int k1 = (int)u1;
                    float2 e1 = stab[k1];
                    float v = fmaf(u1-(float)k1, e1.y, e1.x);
                    sum += ok ? v*rd : 0.f;
                }
            } else {
                #pragma unroll
                for (int t = 1; t < 8; t++) {
                    float d2 = ((t&1)?ax1:ax0) + ((t&2)?ay1:ay0) + ((t&4)?az1:az0);
                    bool ok = d2 < cut2r;
                    float rd = rsqrtf(d2);
                    float dist = d2*rd;
                    float u1 = fminf(dist*c1, TCLAMP);
                    float u2 = fminf(dist*c2, TCLAMP);
                    int k1 = (int)u1, k2 = (int)u2;
                    float2 e1 = stab[k1], e2 = stab[k2];
                    float v = fmaf(u1-(float)k1, e1.y, e1.x)
                            - fmaf(u2-(float)k2, e2.y, e2.x);
                    sum += ok ? v*rd : 0.f;
                }
            }
        } else {
            int two = Ps.twoR, nrr = Ps.nrr, nsh = Ps.nsh;
            for (int s = 0; s < nsh; s++) {
                int a = s/(two*two) - nrr;
                int r2 = s%(two*two);
                int b = r2/two - nrr;
                int c3 = r2%two - nrr;
                float dx = dx0 + a*Ps.cf[0] + b*Ps.cf[3] + c3*Ps.cf[6];
                float dy = dy0 + a*Ps.cf[1] + b*Ps.cf[4] + c3*Ps.cf[7];
                float dz = dz0 + a*Ps.cf[2] + b*Ps.cf[5] + c3*Ps.cf[8];
                float d2 = fmaf(dx,dx, fmaf(dy,dy, dz*dz));
                bool ok = (d2 > EPS2) && (d2 < cut2r);
                float d2c = fmaxf(d2, 1e-12f);
                float rd = rsqrtf(d2c);
                float dist = d2c*rd;
                float u1 = fminf(dist*c1, TCLAMP);
                float u2 = fminf(dist*c2, TCLAMP);
                int k1 = (int)u1, k2 = (int)u2;
                float2 e1 = stab[k1], e2 = stab[k2];
                float v = fmaf(u1-(float)k1, e1.y, e1.x)
                        - fmaf(u2-(float)k2, e2.y, e2.x);
                sum += ok ? v*rd : 0.f;
            }
        }
        return sum;
    };

    auto decode = [&](long long p, int& i, int& j) {
        float tnf = 2.f*(float)n + 1.f;
        long long discl = (long long)(2*n+1)*(2*n+1) - 8*p;
        i = (int)((tnf - sqrtf((float)discl)) * 0.5f);
        if (i < 0) i = 0;
        if (i >= n) i = n - 1;
        long long off = (long long)i*n - (long long)i*(i-1)/2;
        while (p < off) { i--; off = (long long)i*n - (long long)i*(i-1)/2; }
        while (p >= off + (long long)(n - i)) { off += (n - i); i++; }
        j = i + (int)(p - off);
    };

    if (Ps.split) {
        const int nrows = Ps.nrows;
        if (isRecip) {
            // ===== block-cooperative reciprocal row (scalar recurrence) =====
            int row = blockIdx.x;
            int b, cc; float wt;
            if (row == 0)          { b = 0;   cc = 0; wt = 1.f; }
            else if (row <= nr)    { b = row; cc = 0; wt = 2.f; }
            else {
                int t2 = row - 1 - nr, two = 2*nr + 1;
                cc = t2/two + 1; b = t2%two - nr;
                wt = 2.f;
            }
            float ux = b*R10 + cc*R20, uy = b*R11 + cc*R21, uz = b*R12 + cc*R22;
            float s00 = R00*R00 + R01*R01 + R02*R02;
            float s0u = R00*ux + R01*uy + R02*uz;
            float uu  = ux*ux + uy*uy + uz*uz;
            float a1f = floorf(-s0u/s00);
            float mink2 = 1e30f;
            #pragma unroll
            for (int t2 = 0; t2 < 2; t2++) {
                float af = fminf(fmaxf(a1f + t2, -8.f), 8.f);
                mink2 = fminf(mink2, fmaf(af, fmaf(af, s00, 2.f*s0u), uu));
            }
            if (mink2 < cut2k) {
                float Sc[17], Ss[17];
                #pragma unroll
                for (int t2 = 0; t2 < 17; t2++) { Sc[t2]=0.f; Ss[t2]=0.f; }
                float bf = (float)b, cf2 = (float)cc;
                for (int i = tid; i < n; i += 256) {
                    float4 a = sp[i];
                    float th = bf*(R10*a.x + R11*a.y + R12*a.z)
                             + cf2*(R20*a.x + R21*a.y + R22*a.z);
                    float sn, co; __sincosf(th, &sn, &co);
                    float pr = a.w*co, pim = a.w*sn;
                    float mr = pr, mi = pim;
                    float2 u2v = su[i];
                    Sc[8] += pr; Ss[8] += pim;
                    #pragma unroll
                    for (int a2 = 1; a2 <= 8; a2++) {
                        float t1 = pr*u2v.x - pim*u2v.y;
                        pim = pr*u2v.y + pim*u2v.x; pr = t1;
                        Sc[8+a2] += pr; Ss[8+a2] += pim;
                        float t3 = mr*u2v.x + mi*u2v.y;
                        mi = mi*u2v.x - mr*u2v.y; mr = t3;
                        Sc[8-a2] += mr; Ss[8-a2] += mi;
                    }
                }
                #pragma unroll
                for (int v = 0; v < 17; v++) {
                    float scv = Sc[v], ssv = Ss[v];
                    #pragma unroll
                    for (int o = 16; o > 0; o >>= 1) {
                        scv += __shfl_xor_sync(0xffffffffu, scv, o);
                        ssv += __shfl_xor_sync(0xffffffffu, ssv, o);
                    }
                    if (lane == 0) { sred34[v][wrp] = scv; sred34[17+v][wrp] = ssv; }
                }
                __syncthreads();
                if (wrp == 0) {
                    float term = 0.f;
                    if (lane < 17) {
                        float scv = 0.f, ssv = 0.f;
                        #pragma unroll
                        for (int w2 = 0; w2 < 8; w2++) {
                            scv += sred34[lane][w2];
                            ssv += sred34[17+lane][w2];
                        }
                        float af = (float)(lane - 8);
                        float kx = af*R00+ux, ky = af*R01+uy, kz = af*R02+uz;
                        float kl2 = kx*kx + ky*ky + kz*kz;
                        if (kl2 > EPS2 && kl2 < cut2k)
                            term = wt * __expf(-eta2h*kl2) / kl2 * (scv*scv + ssv*ssv);
                    }
                    #pragma unroll
                    for (int o = 16; o > 0; o >>= 1)
                        term += __shfl_xor_sync(0xffffffffu, term, o);
                    if (lane == 0) kacc = (double)term;
                }
            }
        } else {
            // ===== real pairs: contiguous per-block, per-thread chunks =====
            int rb = blockIdx.x - nrows;
            int NB = GRID - nrows;
            long long lo = ((long long)rb * T) / NB;
            long long hi = ((long long)(rb+1) * T) / NB;
            int cnt = (int)(hi - lo);
            int cpt = (cnt + 255) >> 8;
            long long start = lo + (long long)tid * cpt;
            long long end = start + cpt; if (end > hi) end = hi;
            if (start < end) {
                int i, j;
                decode(start, i, j);
                float racc_f = 0.f;
                for (long long p = start; p < end; p++) {
                    float gi = ssig[i];
                    float sum = pair_sum(i, j, gi);
                    float wq = sp[i].w * sp[j].w;
                    if (i == j) racc_f += wq*(sum + self_c + 1.f/(SQRTPI*gi));
                    else        racc_f += 2.f*wq*sum;
                    j++;
                    if (j == n) { i++; j = i; }
                }
                racc = (double)racc_f;
            }
        }
    } else {
        // ===== generic fallback: round-9 scheme =====
        const int gw = (blockIdx.x << 3) + wrp;
        {
            float kacc_f = 0.f;
            const int Ntask = Ps.ntask;
            int t_lo = (int)(((long long)gw * Ntask) / NWARPS);
            int t_hi = (int)(((long long)(gw+1) * Ntask) / NWARPS);
            for (int idx = t_lo; idx < t_hi; idx++) {
                int row = idx >> 1, half = idx & 1;
                int b, cc; float wt;
                if (row == 0)          { b = 0;   cc = 0; wt = 1.f; }
                else if (row <= nr)    { b = row; cc = 0; wt = 2.f; }
                else {
                    int t2 = row - 1 - nr, two = 2*nr + 1;
                    cc = t2/two + 1; b = t2%two - nr;
                    wt = 2.f;
                }
                int alo = half ? -nr : 0;
                int ahi = half ? -1  : nr;
                float ux = b*R10 + cc*R20, uy = b*R11 + cc*R21, uz = b*R12 + cc*R22;
                float s00 = R00*R00 + R01*R01 + R02*R02;
                float s0u = R00*ux + R01*uy + R02*uz;
                float uu  = ux*ux + uy*uy + uz*uz;
                float a1f = floorf(-s0u/s00);
                float mink2 = 1e30f;
                #pragma unroll
                for (int t2 = 0; t2 < 2; t2++) {
                    float af = fminf(fmaxf(a1f + t2, (float)alo), (float)ahi);
                    mink2 = fminf(mink2, fmaf(af, fmaf(af, s00, 2.f*s0u), uu));
                }
                if (mink2 >= cut2k) continue;
                for (int a = alo; a <= ahi; a++) {
                    float af = (float)a;
                    float kx = af*R00+ux, ky = af*R01+uy, kz = af*R02+uz;
                    float kl2 = kx*kx + ky*ky + kz*kz;
                    if (!(kl2 > EPS2 && kl2 < cut2k)) continue;
                    float scv = 0.f, ssv = 0.f;
                    for (int i = lane; i < n; i += 32) {
                        float4 a3 = sp[i];
                        float th = kx*a3.x + ky*a3.y + kz*a3.z;
                        float sn, co; __sincosf(th, &sn, &co);
                        scv = fmaf(a3.w, co, scv);
                        ssv = fmaf(a3.w, sn, ssv);
                    }
                    #pragma unroll
                    for (int o = 16; o > 0; o >>= 1) {
                        scv += __shfl_xor_sync(0xffffffffu, scv, o);
                        ssv += __shfl_xor_sync(0xffffffffu, ssv, o);
                    }
                    if (lane == 0)
                        kacc_f += wt * __expf(-eta2h*kl2) / kl2
                                  * (scv*scv + ssv*ssv);
                }
            }
            kacc = (double)kacc_f;
        }
        {
            const long long CH = 2;
            const long long G2 = (long long)GRID * 256 * CH;
            for (long long p0 = ((long long)blockIdx.x*256 + tid)*CH; p0 < T; p0 += G2) {
                int i, j;
                decode(p0, i, j);
                float racc_f = 0.f;
                #pragma unroll
                for (int u = 0; u < (int)CH; u++) {
                    if (p0 + u >= T) break;
                    float gi = ssig[i];
                    float sum = pair_sum(i, j, gi);
                    float wq = sp[i].w * sp[j].w;
                    if (i == j) racc_f += wq*(sum + self_c + 1.f/(SQRTPI*gi));
                    else        racc_f += 2.f*wq*sum;
                    j++;
                    if (j == n) { i++; j = i; }
                }
                racc += (double)racc_f;
            }
        }
    }

    // ---- reduction ----
    double tot = 0.5*COEF*(racc + (double)Ps.pref4 * kacc);
    #pragma unroll
    for (int o = 16; o > 0; o >>= 1)
        tot += __shfl_xor_sync(0xffffffffu, tot, o);
    __syncthreads();
    if (lane == 0) swred[wrp] = tot;
    __syncthreads();
    if (tid == 0) {
        double s = swred[0]+swred[1]+swred[2]+swred[3]
                 + swred[4]+swred[5]+swred[6]+swred[7];
        atomicAdd(&g_acc, s);
        __threadfence();
        unsigned t = atomicAdd(&g_done, 1u);
        if (t == gridDim.x - 1) {
            double v = atomicAdd(&g_acc, 0.0);
            out[0] = (float)v;
            g_acc = 0.0;
            g_done = 0u;
        }
    }
}

extern "C" void kernel_launch(void* const* d_in, const int* in_sizes, int n_in,
                              void* d_out, int out_size)
{
    const float* pos     = (const float*)d_in[0];
    const float* cell    = (const float*)d_in[1];
    const float* charges = (const float*)d_in[2];
    const float* sigt    = (const float*)d_in[3];
    const int*   spec    = (const int*)d_in[4];
    const int*   nsr     = (const int*)d_in[5];
    const int*   nsk     = (const int*)d_in[6];
    int n = in_sizes[0] / 3;
    int ntyp = in_sizes[3];

    ewald_kernel<<<GRID, 256>>>(pos, cell, charges, sigt, spec, nsr, nsk,
                                (float*)d_out, n, ntyp);
}